// round 2
// baseline (speedup 1.0000x reference)
#include <cuda_runtime.h>
#include <stdint.h>

#define B_ROWS 8192
#define D_DIM  512
#define N_OFF  16

struct OffArgs { int off[N_OFF]; };

// ---------------------------------------------------------------------------
// Warp-per-row, chunk-major: query row resident in 16 regs; for each 128-float
// D-chunk, batch 8 LDG.128 across 8 item rows before consuming them with FMAs.
// Two 8-row half-batches per chunk keep peak live regs ~84.
// ---------------------------------------------------------------------------
__global__ __launch_bounds__(128, 6) void ibns_kernel(
    const float* __restrict__ q,
    const float* __restrict__ items,
    float* __restrict__ out,
    OffArgs oa)
{
    const int gw   = (blockIdx.x * 128 + threadIdx.x) >> 5;   // global warp = row b
    const int lane = threadIdx.x & 31;

    // Query row: 4 chunks x float4/lane = 16 regs, perfectly coalesced.
    const float4* qr = reinterpret_cast<const float4*>(q + (size_t)gw * D_DIM);
    float4 qv[4];
#pragma unroll
    for (int c = 0; c < 4; c++) qv[c] = qr[lane + 32 * c];

    float s[N_OFF];
#pragma unroll
    for (int n = 0; n < N_OFF; n++) s[n] = 0.f;

#pragma unroll
    for (int c = 0; c < 4; c++) {
        const float4 qc = qv[c];
#pragma unroll
        for (int h = 0; h < 2; h++) {           // two half-batches of 8 rows
            float4 v[8];
#pragma unroll
            for (int k = 0; k < 8; k++) {
                const int n = h * 8 + k;
                const int j = (gw + oa.off[n]) & (B_ROWS - 1);
                v[k] = *reinterpret_cast<const float4*>(
                    items + (size_t)j * D_DIM + 128 * c + 4 * lane);
            }
#pragma unroll
            for (int k = 0; k < 8; k++) {
                const int n = h * 8 + k;
                float acc = s[n];
                acc = fmaf(qc.x, v[k].x, acc);
                acc = fmaf(qc.y, v[k].y, acc);
                acc = fmaf(qc.z, v[k].z, acc);
                acc = fmaf(qc.w, v[k].w, acc);
                s[n] = acc;
            }
        }
    }

    // Butterfly reduce each of the 16 partial dots across the warp.
#pragma unroll
    for (int n = 0; n < N_OFF; n++) {
        float v = s[n];
        v += __shfl_xor_sync(0xffffffffu, v, 16);
        v += __shfl_xor_sync(0xffffffffu, v, 8);
        v += __shfl_xor_sync(0xffffffffu, v, 4);
        v += __shfl_xor_sync(0xffffffffu, v, 2);
        v += __shfl_xor_sync(0xffffffffu, v, 1);
        s[n] = v;
    }

    if (lane == 0) {
        float mx = s[0];
#pragma unroll
        for (int n = 1; n < N_OFF; n++) mx = fmaxf(mx, s[n]);
        float denom = 0.f;
#pragma unroll
        for (int n = 0; n < N_OFF; n++) denom += __expf((s[n] - mx) * 10.0f);
        out[gw] = __expf((s[0] - mx) * 10.0f) / denom;
    }
}

// ---------------------------------------------------------------------------
// Host-side exact replication of numpy's
//   np.random.default_rng(0).choice(np.arange(1, 8192), size=15, replace=False)
// SeedSequence(0) -> PCG64 (XSL-RR 128/64) -> Generator.choice Floyd's algorithm
// with hash set + final _shuffle_int. Deterministic, stateless, no allocation.
// ---------------------------------------------------------------------------
namespace ibns_rng {

typedef unsigned __int128 u128;

struct Pcg {
    u128 state, inc;
    int has32;
    uint32_t buf;
};

static inline uint64_t rotr64(uint64_t x, uint32_t r) {
    return (x >> r) | (x << ((64u - r) & 63u));
}

static const u128 PCG_MULT = (((u128)2549297995355413924ULL) << 64) | 4865540595714422341ULL;

static inline uint64_t pcg_next64(Pcg* p) {
    p->state = p->state * PCG_MULT + p->inc;
    uint64_t hi = (uint64_t)(p->state >> 64);
    uint64_t lo = (uint64_t)p->state;
    uint32_t rot = (uint32_t)(p->state >> 122);
    return rotr64(hi ^ lo, rot);
}

static inline uint32_t pcg_next32(Pcg* p) {
    if (p->has32) { p->has32 = 0; return p->buf; }
    uint64_t v = pcg_next64(p);
    p->has32 = 1;
    p->buf = (uint32_t)(v >> 32);
    return (uint32_t)v;
}

// numpy distributions.c bounded_lemire_uint32: inclusive range [0, rng]
static inline uint32_t lemire32(Pcg* p, uint32_t rng) {
    if (rng == 0) return 0;
    const uint32_t rng_excl = rng + 1u;
    uint64_t m = (uint64_t)pcg_next32(p) * (uint64_t)rng_excl;
    uint32_t leftover = (uint32_t)m;
    if (leftover < rng_excl) {
        const uint32_t threshold = (0xFFFFFFFFu - rng) % rng_excl;
        while (leftover < threshold) {
            m = (uint64_t)pcg_next32(p) * (uint64_t)rng_excl;
            leftover = (uint32_t)m;
        }
    }
    return (uint32_t)(m >> 32);
}

// --- SeedSequence constants (numpy bit_generator.pyx, imneme seed_seq_fe) ---
static const uint32_t INIT_A = 0x43b0d7e5u, MULT_A = 0x931e8875u;
static const uint32_t INIT_B = 0x8b51f9ddu, MULT_B = 0x58f38dedu;
static const uint32_t MIX_L  = 0xca01f9ddu, MIX_R  = 0x4973f715u;

static inline uint32_t hashmix(uint32_t v, uint32_t* hc) {
    v ^= *hc;
    *hc = (uint32_t)(*hc * MULT_A);
    v = (uint32_t)(v * *hc);
    v ^= v >> 16;
    return v;
}
static inline uint32_t mixfn(uint32_t x, uint32_t y) {
    uint32_t r = (uint32_t)(MIX_L * x - MIX_R * y);
    r ^= r >> 16;
    return r;
}

static void compute_offsets(int* off16) {
    // SeedSequence(0): entropy = [0], pool_size = 4
    uint32_t pool[4];
    uint32_t hc = INIT_A;
    pool[0] = hashmix(0u, &hc);
    pool[1] = hashmix(0u, &hc);
    pool[2] = hashmix(0u, &hc);
    pool[3] = hashmix(0u, &hc);
    for (int i_src = 0; i_src < 4; i_src++)
        for (int i_dst = 0; i_dst < 4; i_dst++)
            if (i_src != i_dst)
                pool[i_dst] = mixfn(pool[i_dst], hashmix(pool[i_src], &hc));

    // generate_state(4, uint64) == 8 uint32 words, little-endian pairing
    uint32_t w[8];
    hc = INIT_B;
    for (int i = 0; i < 8; i++) {
        uint32_t dv = pool[i & 3];
        dv ^= hc;
        hc = (uint32_t)(hc * MULT_B);
        dv = (uint32_t)(dv * hc);
        dv ^= dv >> 16;
        w[i] = dv;
    }
    uint64_t val[4];
    for (int k = 0; k < 4; k++)
        val[k] = (uint64_t)w[2 * k] | ((uint64_t)w[2 * k + 1] << 32);

    // PCG64 seeding: initstate = (val0<<64)|val1, initseq = (val2<<64)|val3
    u128 initstate = (((u128)val[0]) << 64) | val[1];
    u128 initseq   = (((u128)val[2]) << 64) | val[3];
    Pcg p;
    p.has32 = 0; p.buf = 0;
    p.state = 0;
    p.inc = (initseq << 1) | 1;
    p.state = p.state * PCG_MULT + p.inc;   // step
    p.state += initstate;
    p.state = p.state * PCG_MULT + p.inc;   // step

    // Generator.choice(pop_size=8191, size=15, replace=False, p=None):
    // Floyd's algorithm with hash set (set_size=32, mask=31), then shuffle.
    const int pop_size = 8191, size = 15;
    const uint64_t NONE = ~(uint64_t)0;
    uint64_t hset[32];
    for (int i = 0; i < 32; i++) hset[i] = NONE;
    int64_t idx[15];
    for (int j = pop_size - size; j < pop_size; j++) {
        uint64_t v = (uint64_t)lemire32(&p, (uint32_t)j);   // [0, j]
        uint32_t loc = (uint32_t)(v & 31u);
        while (hset[loc] != NONE && hset[loc] != v) loc = (loc + 1u) & 31u;
        if (hset[loc] == NONE) {
            hset[loc] = v;
            idx[j - (pop_size - size)] = (int64_t)v;
        } else {
            loc = (uint32_t)((uint32_t)j & 31u);
            while (hset[loc] != NONE) loc = (loc + 1u) & 31u;
            hset[loc] = (uint64_t)j;
            idx[j - (pop_size - size)] = (int64_t)j;
        }
    }
    // _shuffle_int(size=15, first=1)
    for (int i = size - 1; i >= 1; i--) {
        uint32_t j = lemire32(&p, (uint32_t)i);
        int64_t t = idx[j]; idx[j] = idx[i]; idx[i] = t;
    }

    // a = arange(1, 8192) -> offset value = idx + 1; prepend 0
    off16[0] = 0;
    for (int n = 0; n < 15; n++) off16[n + 1] = (int)(idx[n] + 1);
}

} // namespace ibns_rng

extern "C" void kernel_launch(void* const* d_in, const int* in_sizes, int n_in,
                              void* d_out, int out_size) {
    (void)in_sizes; (void)n_in; (void)out_size;
    OffArgs oa;
    ibns_rng::compute_offsets(oa.off);

    const float* q     = (const float*)d_in[0];
    const float* items = (const float*)d_in[1];
    float* out         = (float*)d_out;

    // 8192 warps, 4 warps per 128-thread CTA -> 2048 CTAs
    ibns_kernel<<<B_ROWS / 4, 128>>>(q, items, out, oa);
}

// round 3
// speedup vs baseline: 1.0865x; 1.0865x over previous
#include <cuda_runtime.h>
#include <stdint.h>

#define B_ROWS 8192
#define D_DIM  512
#define N_OFF  16

struct OffArgs { int off[N_OFF]; };

// Compressed item planes: 24-bit floats split as hi16 (top 2 bytes of fp32 bits,
// after round-to-nearest on bit 7) and lo8 (byte 1 of the rounded bits).
// Layouts are lane-permuted for coalesced LDG.128 in the main kernel:
//   hi: uint4 index (row*2 + c2)*32 + lane  -> 8 halves: chunk 2c2 k0..k3, chunk 2c2+1 k0..k3
//   lo: uint4 index  row*32 + lane          -> word c = bytes for chunk c, k0..k3
// where element (c,k) = items[row*512 + c*128 + 4*lane + k], matching the
// query float4 loads qv[c] at q + row*512 + c*128 + 4*lane.
__device__ uint4 g_hi[B_ROWS * 64];   // 8192*512*2B = 8 MB
__device__ uint4 g_lo[B_ROWS * 32];   // 8192*512*1B = 4 MB

// ---------------------------------------------------------------------------
// Prepass: warp per item row; round fp32 -> 24-bit and write split planes.
// ---------------------------------------------------------------------------
__global__ __launch_bounds__(128) void ibns_pack_kernel(const float* __restrict__ items)
{
    const int row  = (blockIdx.x * 128 + threadIdx.x) >> 5;
    const int lane = threadIdx.x & 31;

    uint32_t u[4][4];   // [chunk][k] rounded fp32 bits
#pragma unroll
    for (int c = 0; c < 4; c++) {
        const float4 v = *reinterpret_cast<const float4*>(
            items + (size_t)row * D_DIM + 128 * c + 4 * lane);
        u[c][0] = __float_as_uint(v.x) + 0x80u;
        u[c][1] = __float_as_uint(v.y) + 0x80u;
        u[c][2] = __float_as_uint(v.z) + 0x80u;
        u[c][3] = __float_as_uint(v.w) + 0x80u;
    }

    // hi planes: two uint4 per row-lane
#pragma unroll
    for (int c2 = 0; c2 < 2; c2++) {
        uint4 h;
        h.x = (u[2*c2][0]   >> 16) | (u[2*c2][1]   & 0xFFFF0000u);
        h.y = (u[2*c2][2]   >> 16) | (u[2*c2][3]   & 0xFFFF0000u);
        h.z = (u[2*c2+1][0] >> 16) | (u[2*c2+1][1] & 0xFFFF0000u);
        h.w = (u[2*c2+1][2] >> 16) | (u[2*c2+1][3] & 0xFFFF0000u);
        g_hi[(row * 2 + c2) * 32 + lane] = h;
    }

    // lo plane: one uint4 per row-lane; word c = 4 lo-bytes of chunk c
    uint4 l;
    uint32_t* lw = &l.x;
#pragma unroll
    for (int c = 0; c < 4; c++) {
        lw[c] = ((u[c][0] >> 8) & 0xFFu)
              | ((u[c][1]      ) & 0xFF00u)
              | ((u[c][2] <<  8) & 0xFF0000u)
              | ((u[c][3] << 16) & 0xFF000000u);
    }
    g_lo[row * 32 + lane] = l;
}

// Reconstruct the 4 elements of one chunk from a hi-word-pair (w01 = k0|k1<<16,
// w23 = k2|k3<<16) and the chunk's lo word, and FMA them against qc.
__device__ __forceinline__ float chunk_fma(float acc, float4 qc,
                                           uint32_t w01, uint32_t w23, uint32_t lw)
{
    const uint32_t t1 = lw << 8;      // lo byte0 at pos1
    const uint32_t t3 = lw >> 8;      // lo byte2 at pos1 (after mask)
    float e0 = __uint_as_float((w01 << 16)          | (t1 & 0xFF00u));
    float e1 = __uint_as_float((w01 & 0xFFFF0000u)  | (lw & 0xFF00u));
    float e2 = __uint_as_float((w23 << 16)          | (t3 & 0xFF00u));
    float e3 = __uint_as_float((w23 & 0xFFFF0000u)  | ((lw >> 16) & 0xFF00u));
    acc = fmaf(qc.x, e0, acc);
    acc = fmaf(qc.y, e1, acc);
    acc = fmaf(qc.z, e2, acc);
    acc = fmaf(qc.w, e3, acc);
    return acc;
}

// ---------------------------------------------------------------------------
// Main kernel: warp per query row; 16 item rows read from 24-bit planes
// (3 LDG.128 per row per lane), batched 2 rows at a time for MLP.
// ---------------------------------------------------------------------------
__global__ __launch_bounds__(128, 6) void ibns_kernel(
    const float* __restrict__ q,
    float* __restrict__ out,
    OffArgs oa)
{
    const int gw   = (blockIdx.x * 128 + threadIdx.x) >> 5;
    const int lane = threadIdx.x & 31;

    const float4* qr = reinterpret_cast<const float4*>(q + (size_t)gw * D_DIM);
    float4 qv[4];
#pragma unroll
    for (int c = 0; c < 4; c++) qv[c] = qr[lane + 32 * c];

    float s[N_OFF];
#pragma unroll
    for (int n = 0; n < N_OFF; n++) s[n] = 0.f;

#pragma unroll
    for (int p = 0; p < 8; p++) {       // 8 pairs of rows
        uint4 H0[2], H1[2], L[2];
#pragma unroll
        for (int r = 0; r < 2; r++) {
            const int n = 2 * p + r;
            const int j = (gw + oa.off[n]) & (B_ROWS - 1);
            H0[r] = g_hi[(j * 2 + 0) * 32 + lane];
            H1[r] = g_hi[(j * 2 + 1) * 32 + lane];
            L[r]  = g_lo[j * 32 + lane];
        }
#pragma unroll
        for (int r = 0; r < 2; r++) {
            const int n = 2 * p + r;
            float acc = s[n];
            acc = chunk_fma(acc, qv[0], H0[r].x, H0[r].y, L[r].x);
            acc = chunk_fma(acc, qv[1], H0[r].z, H0[r].w, L[r].y);
            acc = chunk_fma(acc, qv[2], H1[r].x, H1[r].y, L[r].z);
            acc = chunk_fma(acc, qv[3], H1[r].z, H1[r].w, L[r].w);
            s[n] = acc;
        }
    }

#pragma unroll
    for (int n = 0; n < N_OFF; n++) {
        float v = s[n];
        v += __shfl_xor_sync(0xffffffffu, v, 16);
        v += __shfl_xor_sync(0xffffffffu, v, 8);
        v += __shfl_xor_sync(0xffffffffu, v, 4);
        v += __shfl_xor_sync(0xffffffffu, v, 2);
        v += __shfl_xor_sync(0xffffffffu, v, 1);
        s[n] = v;
    }

    if (lane == 0) {
        float mx = s[0];
#pragma unroll
        for (int n = 1; n < N_OFF; n++) mx = fmaxf(mx, s[n]);
        float denom = 0.f;
#pragma unroll
        for (int n = 0; n < N_OFF; n++) denom += __expf((s[n] - mx) * 10.0f);
        out[gw] = __expf((s[0] - mx) * 10.0f) / denom;
    }
}

// ---------------------------------------------------------------------------
// Host-side exact replication of numpy's
//   np.random.default_rng(0).choice(np.arange(1, 8192), size=15, replace=False)
// SeedSequence(0) -> PCG64 (XSL-RR 128/64) -> Generator.choice Floyd's algorithm
// with hash set + final _shuffle_int. Deterministic, stateless, no allocation.
// ---------------------------------------------------------------------------
namespace ibns_rng {

typedef unsigned __int128 u128;

struct Pcg {
    u128 state, inc;
    int has32;
    uint32_t buf;
};

static inline uint64_t rotr64(uint64_t x, uint32_t r) {
    return (x >> r) | (x << ((64u - r) & 63u));
}

static const u128 PCG_MULT = (((u128)2549297995355413924ULL) << 64) | 4865540595714422341ULL;

static inline uint64_t pcg_next64(Pcg* p) {
    p->state = p->state * PCG_MULT + p->inc;
    uint64_t hi = (uint64_t)(p->state >> 64);
    uint64_t lo = (uint64_t)p->state;
    uint32_t rot = (uint32_t)(p->state >> 122);
    return rotr64(hi ^ lo, rot);
}

static inline uint32_t pcg_next32(Pcg* p) {
    if (p->has32) { p->has32 = 0; return p->buf; }
    uint64_t v = pcg_next64(p);
    p->has32 = 1;
    p->buf = (uint32_t)(v >> 32);
    return (uint32_t)v;
}

static inline uint32_t lemire32(Pcg* p, uint32_t rng) {
    if (rng == 0) return 0;
    const uint32_t rng_excl = rng + 1u;
    uint64_t m = (uint64_t)pcg_next32(p) * (uint64_t)rng_excl;
    uint32_t leftover = (uint32_t)m;
    if (leftover < rng_excl) {
        const uint32_t threshold = (0xFFFFFFFFu - rng) % rng_excl;
        while (leftover < threshold) {
            m = (uint64_t)pcg_next32(p) * (uint64_t)rng_excl;
            leftover = (uint32_t)m;
        }
    }
    return (uint32_t)(m >> 32);
}

static const uint32_t INIT_A = 0x43b0d7e5u, MULT_A = 0x931e8875u;
static const uint32_t INIT_B = 0x8b51f9ddu, MULT_B = 0x58f38dedu;
static const uint32_t MIX_L  = 0xca01f9ddu, MIX_R  = 0x4973f715u;

static inline uint32_t hashmix(uint32_t v, uint32_t* hc) {
    v ^= *hc;
    *hc = (uint32_t)(*hc * MULT_A);
    v = (uint32_t)(v * *hc);
    v ^= v >> 16;
    return v;
}
static inline uint32_t mixfn(uint32_t x, uint32_t y) {
    uint32_t r = (uint32_t)(MIX_L * x - MIX_R * y);
    r ^= r >> 16;
    return r;
}

static void compute_offsets(int* off16) {
    uint32_t pool[4];
    uint32_t hc = INIT_A;
    pool[0] = hashmix(0u, &hc);
    pool[1] = hashmix(0u, &hc);
    pool[2] = hashmix(0u, &hc);
    pool[3] = hashmix(0u, &hc);
    for (int i_src = 0; i_src < 4; i_src++)
        for (int i_dst = 0; i_dst < 4; i_dst++)
            if (i_src != i_dst)
                pool[i_dst] = mixfn(pool[i_dst], hashmix(pool[i_src], &hc));

    uint32_t w[8];
    hc = INIT_B;
    for (int i = 0; i < 8; i++) {
        uint32_t dv = pool[i & 3];
        dv ^= hc;
        hc = (uint32_t)(hc * MULT_B);
        dv = (uint32_t)(dv * hc);
        dv ^= dv >> 16;
        w[i] = dv;
    }
    uint64_t val[4];
    for (int k = 0; k < 4; k++)
        val[k] = (uint64_t)w[2 * k] | ((uint64_t)w[2 * k + 1] << 32);

    u128 initstate = (((u128)val[0]) << 64) | val[1];
    u128 initseq   = (((u128)val[2]) << 64) | val[3];
    Pcg p;
    p.has32 = 0; p.buf = 0;
    p.state = 0;
    p.inc = (initseq << 1) | 1;
    p.state = p.state * PCG_MULT + p.inc;
    p.state += initstate;
    p.state = p.state * PCG_MULT + p.inc;

    const int pop_size = 8191, size = 15;
    const uint64_t NONE = ~(uint64_t)0;
    uint64_t hset[32];
    for (int i = 0; i < 32; i++) hset[i] = NONE;
    int64_t idx[15];
    for (int j = pop_size - size; j < pop_size; j++) {
        uint64_t v = (uint64_t)lemire32(&p, (uint32_t)j);
        uint32_t loc = (uint32_t)(v & 31u);
        while (hset[loc] != NONE && hset[loc] != v) loc = (loc + 1u) & 31u;
        if (hset[loc] == NONE) {
            hset[loc] = v;
            idx[j - (pop_size - size)] = (int64_t)v;
        } else {
            loc = (uint32_t)((uint32_t)j & 31u);
            while (hset[loc] != NONE) loc = (loc + 1u) & 31u;
            hset[loc] = (uint64_t)j;
            idx[j - (pop_size - size)] = (int64_t)j;
        }
    }
    for (int i = size - 1; i >= 1; i--) {
        uint32_t j = lemire32(&p, (uint32_t)i);
        int64_t t = idx[j]; idx[j] = idx[i]; idx[i] = t;
    }

    off16[0] = 0;
    for (int n = 0; n < 15; n++) off16[n + 1] = (int)(idx[n] + 1);
}

} // namespace ibns_rng

extern "C" void kernel_launch(void* const* d_in, const int* in_sizes, int n_in,
                              void* d_out, int out_size) {
    (void)in_sizes; (void)n_in; (void)out_size;
    OffArgs oa;
    ibns_rng::compute_offsets(oa.off);

    const float* q     = (const float*)d_in[0];
    const float* items = (const float*)d_in[1];
    float* out         = (float*)d_out;

    ibns_pack_kernel<<<B_ROWS / 4, 128>>>(items);
    ibns_kernel<<<B_ROWS / 4, 128>>>(q, out, oa);
}